// round 12
// baseline (speedup 1.0000x reference)
#include <cuda_runtime.h>
#include <cuda_fp16.h>
#include <math.h>
#include <stdint.h>

// Problem constants (fixed shapes)
#define BT   32768      // B*T
#define Dm   128
#define Hh   64
#define Kc   2048

#define MROWS  224      // max A rows per CTA (7 subtiles of 32; max ntok 223 at grid>=147)
#define NSUB   7
#define CHUNK  128      // codes per B chunk
#define NCHK   (Kc / CHUNK)    // 16
#define KPAD   192      // concatenated K (3 segments of 64: hh, mh, hm)
#define KIT    (KPAD / 16)     // 12 k-iterations
#define SA     200      // smem row stride in halves (400B; 400%128=16 -> ldsm conflict-free)

// Output layout (float32 tuple: out, ids, commitment, codebook)
#define OUT_IDS   (BT * Hh)
#define OUT_COMM  (OUT_IDS + BT)
#define OUT_CODE  (OUT_COMM + BT)

// Device scratch
__device__ __align__(16) float g_a[Kc];
__device__ __align__(16) float g_b[Kc];
// B_cat: per code 192 fp16 = segments [wh, wh, wm] of (16*w_d)
__device__ __align__(16) __half g_bcat[Kc * KPAD];

// --------------------------------------------------------------------------
// PTX helpers — all plain sm_80-era features (legal on target compute_103)
// --------------------------------------------------------------------------
__device__ __forceinline__ uint32_t smem_u32(const void* p) {
    uint32_t a;
    asm("{ .reg .u64 t; cvta.to.shared.u64 t, %1; cvt.u32.u64 %0, t; }"
        : "=r"(a) : "l"(p));
    return a;
}
__device__ __forceinline__ void cp16s(uint32_t dst, const void* src) {
    asm volatile("cp.async.cg.shared.global [%0], [%1], 16;" :: "r"(dst), "l"(src));
}
__device__ __forceinline__ void cp_commit() { asm volatile("cp.async.commit_group;"); }
__device__ __forceinline__ void cp_wait1()  { asm volatile("cp.async.wait_group 1;" ::: "memory"); }
__device__ __forceinline__ void cp_wait0()  { asm volatile("cp.async.wait_group 0;" ::: "memory"); }

__device__ __forceinline__ void ldsm4(uint32_t* r, uint32_t addr) {
    asm volatile("ldmatrix.sync.aligned.m8n8.x4.shared.b16 {%0,%1,%2,%3}, [%4];"
        : "=r"(r[0]), "=r"(r[1]), "=r"(r[2]), "=r"(r[3]) : "r"(addr));
}
__device__ __forceinline__ void mma16816(float* d, const uint32_t* a, const uint32_t* b) {
    asm volatile(
        "mma.sync.aligned.m16n8k16.row.col.f32.f16.f16.f32 "
        "{%0,%1,%2,%3}, {%4,%5,%6,%7}, {%8,%9}, {%0,%1,%2,%3};"
        : "+f"(d[0]), "+f"(d[1]), "+f"(d[2]), "+f"(d[3])
        : "r"(a[0]), "r"(a[1]), "r"(a[2]), "r"(a[3]), "r"(b[0]), "r"(b[1]));
}

// --------------------------------------------------------------------------
// Kernel 1: merged prologue. One warp per code (8 codes / 256-thread block).
//   a_k = 1/(2*sum exp(w_lv)),  b_k = 0.5*sum(w_lv) + ||mu_e||^2 * a_k
//   B_cat limbs of 16*w: segments [wh, wh, wm]
// --------------------------------------------------------------------------
__global__ __launch_bounds__(256) void prologue_kernel(const float* __restrict__ emb) {
    int k    = blockIdx.x * 8 + (threadIdx.x >> 5);
    int lane = threadIdx.x & 31;
    if (k >= Kc) return;
    const float* row = emb + (size_t)k * Dm;
    float2 mu = *(const float2*)(row + 2 * lane);
    float2 lv = *(const float2*)(row + Hh + 2 * lane);

    // bcat limbs for dims 2*lane, 2*lane+1
    {
        __half* o = g_bcat + (size_t)k * KPAD;
        float s0 = 16.0f * mu.x, s1 = 16.0f * mu.y;
        __half h0 = __float2half_rn(s0), h1 = __float2half_rn(s1);
        __half m0 = __float2half_rn(s0 - __half2float(h0));
        __half m1 = __float2half_rn(s1 - __half2float(h1));
        __half2* o2 = (__half2*)o;
        o2[(0 * Hh >> 1) + lane] = __halves2half2(h0, h1);
        o2[(1 * Hh >> 1) + lane] = __halves2half2(h0, h1);
        o2[(2 * Hh >> 1) + lane] = __halves2half2(m0, m1);
    }

    float e2 = mu.x * mu.x + mu.y * mu.y;
    float se = expf(lv.x) + expf(lv.y);
    float sl = lv.x + lv.y;
    #pragma unroll
    for (int o = 16; o; o >>= 1) {
        e2 += __shfl_xor_sync(0xffffffffu, e2, o);
        se += __shfl_xor_sync(0xffffffffu, se, o);
        sl += __shfl_xor_sync(0xffffffffu, sl, o);
    }
    if (lane == 0) {
        float a = 0.5f / se;
        g_a[k] = a;
        g_b[k] = 0.5f * sl + e2 * a;
    }
}

// --------------------------------------------------------------------------
// Kernel 2: persistent HMMA argmin + fused epilogue. grid = #SMs, 256 thr.
// CTA owns tokens [t0, t1) (<=223), padded to 7 m32-subtiles (224 rows).
// A (224 x 192 fp16, stride 200) in smem; B chunks (128 codes x 192)
// double-buffered via cp.async. 8 warps: each covers m32 x n16 per subtile.
// dot_acc = 256 * dot;  score = a*(Ci - dot_acc/128) + b.
// --------------------------------------------------------------------------
__device__ __forceinline__ void prefetch_b(uint32_t bbase, int c0, int tid) {
    #pragma unroll
    for (int q = 0; q < 12; q++) {
        int idx = tid + 256 * q;          // 0..3071 16B units
        int row = idx / 24, u = idx % 24;
        cp16s(bbase + row * (SA * 2) + u * 16,
              g_bcat + ((size_t)(c0 + row) * KPAD + u * 8));
    }
}

__global__ __launch_bounds__(256, 1) void argmin_mma_kernel(const float* __restrict__ x,
                                                            const float* __restrict__ emb,
                                                            const float* __restrict__ z,
                                                            float* __restrict__ out) {
    extern __shared__ __half sm[];
    // layout (halves): A[224*200] | B0[128*200] | B1[128*200] | ab(4096 f32) | Ci(224 f32)
    const int A_H = MROWS * SA;
    float* ab   = (float*)(sm + A_H + 2 * CHUNK * SA);
    float* Ci_s = ab + 2 * Kc;
    // post-loop aliases (regions no longer live):
    float* sred_s = (float*)(sm + A_H);            // [8][MROWS] in B0
    int*   sred_i = (int*)(sm + A_H) + 8 * MROWS;
    int*   ids_s  = (int*)Ci_s;

    int tid  = threadIdx.x;
    int warp = tid >> 5, lane = tid & 31;
    int G    = gridDim.x;
    int t0   = (int)(((long long)BT * blockIdx.x) / G);
    int t1   = (int)(((long long)BT * (blockIdx.x + 1)) / G);
    int ntok = t1 - t0;

    uint32_t smbase = smem_u32(sm);
    uint32_t b0a = smbase + A_H * 2;
    uint32_t b1a = b0a + CHUNK * SA * 2;

    // chunk-0 B prefetch first (overlaps A build)
    prefetch_b(b0a, 0, tid);
    cp_commit();

    // a/b tables -> smem
    {
        const float4* ga4 = (const float4*)g_a;
        const float4* gb4 = (const float4*)g_b;
        #pragma unroll
        for (int q = 0; q < 2; q++) ((float4*)ab)[tid + 256 * q]        = ga4[tid + 256 * q];
        #pragma unroll
        for (int q = 0; q < 2; q++) ((float4*)(ab + Kc))[tid + 256 * q] = gb4[tid + 256 * q];
    }

    // A build: row tid (token t0+tid if valid, else zeros)
    if (tid < MROWS) {
        __half2* arow = (__half2*)(sm + tid * SA);
        if (tid < ntok) {
            const float* xr = x + (size_t)(t0 + tid) * Dm;
            float Ci = 0.0f;
            #pragma unroll
            for (int d = 0; d < Hh; d += 2) {
                float2 v = *(const float2*)(xr + d);
                Ci += v.x * v.x + v.y * v.y;
                float s0 = 16.0f * v.x, s1 = 16.0f * v.y;
                __half h0 = __float2half_rn(s0), h1 = __float2half_rn(s1);
                __half m0 = __float2half_rn(s0 - __half2float(h0));
                __half m1 = __float2half_rn(s1 - __half2float(h1));
                __half2 hh = __halves2half2(h0, h1);
                __half2 mm = __halves2half2(m0, m1);
                arow[(0 * Hh + d) >> 1] = hh;
                arow[(1 * Hh + d) >> 1] = mm;
                arow[(2 * Hh + d) >> 1] = hh;
            }
            #pragma unroll
            for (int d = 0; d < Hh; d += 4) {
                float4 v = *(const float4*)(xr + Hh + d);
                Ci += expf(v.x) + expf(v.y) + expf(v.z) + expf(v.w);
            }
            Ci_s[tid] = Ci;
        } else {
            #pragma unroll
            for (int q = 0; q < KPAD / 2; q++) arow[q] = __halves2half2(__ushort_as_half(0), __ushort_as_half(0));
            Ci_s[tid] = 0.0f;
        }
    }
    __syncthreads();   // A_s, ab, Ci_s ready

    // per-lane ldsm offsets
    // A: rows (sub*32 + wmhalf*16) + (lane&15), koff (lane>>4)*16B
    uint32_t a_base = smbase + ((lane & 15) * SA + (lane >> 4) * 8) * 2;
    // B: rows wn*16 + (lane&7) + ((lane>>4)<<3), koff ((lane>>3)&1)*16B
    uint32_t b_off = ((warp * 16 + (lane & 7) + ((lane >> 4) << 3)) * SA
                    + ((lane >> 3) & 1) * 8) * 2;

    int g  = lane >> 2, tc = lane & 3;

    float best[NSUB][4];
    int   bidx[NSUB][4];
    #pragma unroll
    for (int s = 0; s < NSUB; s++)
        #pragma unroll
        for (int q = 0; q < 4; q++) { best[s][q] = 3.4e38f; bidx[s][q] = 0; }

    for (int ch = 0; ch < NCHK; ch++) {
        uint32_t bb = (ch & 1) ? b1a : b0a;

        if (ch < NCHK - 1) {
            prefetch_b((ch & 1) ? b0a : b1a, (ch + 1) * CHUNK, tid);
            cp_commit();
            cp_wait1();           // chunk ch landed
        } else {
            cp_wait0();
        }
        __syncthreads();          // visible block-wide

        #pragma unroll
        for (int sub = 0; sub < NSUB; sub++) {
            float acc[2][2][4];
            #pragma unroll
            for (int mt = 0; mt < 2; mt++)
                #pragma unroll
                for (int nt = 0; nt < 2; nt++)
                    #pragma unroll
                    for (int c = 0; c < 4; c++) acc[mt][nt][c] = 0.0f;

            uint32_t a0 = a_base + (uint32_t)(sub * 32) * (SA * 2);
            uint32_t a1 = a0 + 16 * SA * 2;

            #pragma unroll 1
            for (int k = 0; k < KIT; k++) {
                uint32_t kb = (uint32_t)k * 32;       // 16 halves
                uint32_t af0[4], af1[4], bf[4];
                ldsm4(af0, a0 + kb);
                ldsm4(af1, a1 + kb);
                ldsm4(bf, bb + b_off + kb);
                mma16816(acc[0][0], af0, bf + 0);
                mma16816(acc[0][1], af0, bf + 2);
                mma16816(acc[1][0], af1, bf + 0);
                mma16816(acc[1][1], af1, bf + 2);
            }

            // fold scores (codes ascending; strict < keeps first min)
            int cb = ch * CHUNK + warp * 16 + 2 * tc;
            float CiA[4];
            #pragma unroll
            for (int q = 0; q < 4; q++)
                CiA[q] = Ci_s[sub * 32 + (q >> 1) * 16 + (q & 1) * 8 + g];
            #pragma unroll
            for (int nt = 0; nt < 2; nt++) {
                int c0 = cb + nt * 8;
                float a0v = ab[c0],     b0v = ab[Kc + c0];
                float a1v = ab[c0 + 1], b1v = ab[Kc + c0 + 1];
                #pragma unroll
                for (int mt = 0; mt < 2; mt++)
                    #pragma unroll
                    for (int c = 0; c < 4; c++) {
                        int slot = mt * 2 + (c >> 1);
                        float aa  = (c & 1) ? a1v : a0v;
                        float bbv = (c & 1) ? b1v : b0v;
                        float s = fmaf(aa, fmaf(-0.0078125f, acc[mt][nt][c], CiA[slot]), bbv);
                        int code = c0 + (c & 1);
                        if (s < best[sub][slot]) { best[sub][slot] = s; bidx[sub][slot] = code; }
                    }
            }
        }
        __syncthreads();          // all reads of bb done before it is overwritten
    }

    // reduce across the 4 tc-lanes sharing each token row; stage per-warp
    #pragma unroll
    for (int sub = 0; sub < NSUB; sub++)
        #pragma unroll
        for (int s = 0; s < 4; s++) {
            float v = best[sub][s];
            int   c = bidx[sub][s];
            #pragma unroll
            for (int o = 1; o < 4; o <<= 1) {
                float v2 = __shfl_xor_sync(0xffffffffu, v, o);
                int   c2 = __shfl_xor_sync(0xffffffffu, c, o);
                if (v2 < v || (v2 == v && c2 < c)) { v = v2; c = c2; }
            }
            if (tc == 0) {
                int row = sub * 32 + (s >> 1) * 16 + (s & 1) * 8 + g;
                sred_s[warp * MROWS + row] = v;
                sred_i[warp * MROWS + row] = c;
            }
        }
    __syncthreads();

    if (tid < MROWS) {
        float v = sred_s[tid];
        int   c = sred_i[tid];
        #pragma unroll
        for (int w = 1; w < 8; w++) {
            float v2 = sred_s[w * MROWS + tid];
            int   c2 = sred_i[w * MROWS + tid];
            if (v2 < v || (v2 == v && c2 < c)) { v = v2; c = c2; }
        }
        ids_s[tid] = c;
    }
    __syncthreads();

    // ---- fused epilogue: one warp per token ----
    for (int t = warp; t < ntok; t += 8) {
        int token = t0 + t;
        int id = ids_s[t];
        const float* w  = emb + (size_t)id * Dm;
        const float* xr = x + (size_t)token * Dm;

        float4 wv = *(const float4*)(w  + lane * 4);
        float4 xv = *(const float4*)(xr + lane * 4);
        float d0 = wv.x - xv.x, d1 = wv.y - xv.y, d2 = wv.z - xv.z, d3 = wv.w - xv.w;
        float p = d0 * d0 + d1 * d1 + d2 * d2 + d3 * d3;
        #pragma unroll
        for (int o = 16; o; o >>= 1) p += __shfl_xor_sync(0xffffffffu, p, o);

        #pragma unroll
        for (int r = 0; r < 2; r++) {
            int h = lane + 32 * r;
            float mu = w[h];
            float lv = w[Hh + h];
            float zz = z[(size_t)token * Hh + h];
            out[(size_t)token * Hh + h] = fmaf(expf(0.5f * lv), zz, mu);
        }
        if (lane == 0) {
            float m = p * (1.0f / (float)Dm);
            out[OUT_IDS  + token] = (float)id;
            out[OUT_COMM + token] = m;
            out[OUT_CODE + token] = m;
        }
    }
}

// --------------------------------------------------------------------------
extern "C" void kernel_launch(void* const* d_in, const int* in_sizes, int n_in,
                              void* d_out, int out_size) {
    const float *x = nullptr, *emb = nullptr, *z = nullptr;
    for (int i = 0; i < n_in; i++) {
        if (in_sizes[i] == BT * Dm)      x   = (const float*)d_in[i];
        else if (in_sizes[i] == Kc * Dm) emb = (const float*)d_in[i];
        else if (in_sizes[i] == BT * Hh) z   = (const float*)d_in[i];
    }
    float* out = (float*)d_out;

    int nsm = 148;
    cudaDeviceGetAttribute(&nsm, cudaDevAttrMultiProcessorCount, 0);
    if (nsm < 147) nsm = 147;   // MROWS=224 supports ntok <= 223

    // dyn smem: (224 + 2*128) rows * 200 halves + ab tables + Ci
    const int SMEM_BYTES = (MROWS + 2 * CHUNK) * SA * 2 + 2 * Kc * 4 + MROWS * 4;
    cudaFuncSetAttribute(argmin_mma_kernel,
                         cudaFuncAttributeMaxDynamicSharedMemorySize, SMEM_BYTES);

    prologue_kernel<<<Kc / 8, 256>>>(emb);
    argmin_mma_kernel<<<nsm, 256, SMEM_BYTES>>>(x, emb, z, out);
    (void)out_size;
}

// round 13
// speedup vs baseline: 1.1333x; 1.1333x over previous
#include <cuda_runtime.h>
#include <cuda_fp16.h>
#include <math.h>
#include <stdint.h>

// Problem constants (fixed shapes)
#define BT   32768      // B*T
#define Dm   128
#define Hh   64
#define Kc   2048

#define MROWS  224      // max A rows per CTA (7 subtiles of 32; max ntok 223 at grid>=147)
#define NSUB   7
#define CHUNK  128      // codes per B chunk
#define NCHK   (Kc / CHUNK)    // 16
#define KPAD   192      // concatenated K (3 segments of 64: hh, mh, hm)
#define KIT    (KPAD / 16)     // 12 k-iterations
#define SA     200      // smem row stride in halves (400B; 400%128=16 -> ldsm conflict-free)

// Output layout (float32 tuple: out, ids, commitment, codebook)
#define OUT_IDS   (BT * Hh)
#define OUT_COMM  (OUT_IDS + BT)
#define OUT_CODE  (OUT_COMM + BT)

// Device scratch
__device__ __align__(16) float g_a[Kc];
__device__ __align__(16) float g_b[Kc];
// B_cat: per code 192 fp16 = segments [wh, wh, wm] of (16*w_d)
__device__ __align__(16) __half g_bcat[Kc * KPAD];

// --------------------------------------------------------------------------
// PTX helpers — all plain sm_80-era features (legal on target compute_103)
// --------------------------------------------------------------------------
__device__ __forceinline__ uint32_t smem_u32(const void* p) {
    uint32_t a;
    asm("{ .reg .u64 t; cvta.to.shared.u64 t, %1; cvt.u32.u64 %0, t; }"
        : "=r"(a) : "l"(p));
    return a;
}
__device__ __forceinline__ void cp16s(uint32_t dst, const void* src) {
    asm volatile("cp.async.cg.shared.global [%0], [%1], 16;" :: "r"(dst), "l"(src));
}
__device__ __forceinline__ void cp_commit() { asm volatile("cp.async.commit_group;"); }
__device__ __forceinline__ void cp_wait1()  { asm volatile("cp.async.wait_group 1;" ::: "memory"); }
__device__ __forceinline__ void cp_wait0()  { asm volatile("cp.async.wait_group 0;" ::: "memory"); }

__device__ __forceinline__ void ldsm4(uint32_t* r, uint32_t addr) {
    asm volatile("ldmatrix.sync.aligned.m8n8.x4.shared.b16 {%0,%1,%2,%3}, [%4];"
        : "=r"(r[0]), "=r"(r[1]), "=r"(r[2]), "=r"(r[3]) : "r"(addr));
}
__device__ __forceinline__ void mma16816(float* d, const uint32_t* a, const uint32_t* b) {
    asm volatile(
        "mma.sync.aligned.m16n8k16.row.col.f32.f16.f16.f32 "
        "{%0,%1,%2,%3}, {%4,%5,%6,%7}, {%8,%9}, {%0,%1,%2,%3};"
        : "+f"(d[0]), "+f"(d[1]), "+f"(d[2]), "+f"(d[3])
        : "r"(a[0]), "r"(a[1]), "r"(a[2]), "r"(a[3]), "r"(b[0]), "r"(b[1]));
}

// --------------------------------------------------------------------------
// Kernel 1: merged prologue. One warp per code (8 codes / 256-thread block).
//   a_k = 1/(2*sum exp(w_lv)),  b_k = 0.5*sum(w_lv) + ||mu_e||^2 * a_k
//   B_cat limbs of 16*w: segments [wh, wh, wm]
// --------------------------------------------------------------------------
__global__ __launch_bounds__(256) void prologue_kernel(const float* __restrict__ emb) {
    int k    = blockIdx.x * 8 + (threadIdx.x >> 5);
    int lane = threadIdx.x & 31;
    if (k >= Kc) return;
    const float* row = emb + (size_t)k * Dm;
    float2 mu = *(const float2*)(row + 2 * lane);
    float2 lv = *(const float2*)(row + Hh + 2 * lane);

    {
        __half* o = g_bcat + (size_t)k * KPAD;
        float s0 = 16.0f * mu.x, s1 = 16.0f * mu.y;
        __half h0 = __float2half_rn(s0), h1 = __float2half_rn(s1);
        __half m0 = __float2half_rn(s0 - __half2float(h0));
        __half m1 = __float2half_rn(s1 - __half2float(h1));
        __half2* o2 = (__half2*)o;
        o2[(0 * Hh >> 1) + lane] = __halves2half2(h0, h1);
        o2[(1 * Hh >> 1) + lane] = __halves2half2(h0, h1);
        o2[(2 * Hh >> 1) + lane] = __halves2half2(m0, m1);
    }

    float e2 = mu.x * mu.x + mu.y * mu.y;
    float se = expf(lv.x) + expf(lv.y);
    float sl = lv.x + lv.y;
    #pragma unroll
    for (int o = 16; o; o >>= 1) {
        e2 += __shfl_xor_sync(0xffffffffu, e2, o);
        se += __shfl_xor_sync(0xffffffffu, se, o);
        sl += __shfl_xor_sync(0xffffffffu, sl, o);
    }
    if (lane == 0) {
        float a = 0.5f / se;
        g_a[k] = a;
        g_b[k] = 0.5f * sl + e2 * a;
    }
}

// --------------------------------------------------------------------------
// Kernel 2: persistent HMMA argmin + fused epilogue. grid = #SMs, 256 thr.
// CTA owns tokens [t0, t1) (<=223), padded to 7 m32-subtiles.
// Warp roles: wn = warp&3 owns codes [wn*32, wn*32+32) of the chunk;
// wg = warp>>2 owns subtiles sub ≡ wg (mod 2).
// Per chunk: preload ALL 12 k-iters of B frags into registers (24 ldsm),
// then per subtile: 2 A-ldsm + 8 MMA per k. Fold mapping identical to R9.
// --------------------------------------------------------------------------
__device__ __forceinline__ void prefetch_b(uint32_t bbase, int c0, int tid) {
    #pragma unroll
    for (int q = 0; q < 12; q++) {
        int idx = tid + 256 * q;          // 0..3071 16B units
        int row = idx / 24, u = idx % 24;
        cp16s(bbase + row * (SA * 2) + u * 16,
              g_bcat + ((size_t)(c0 + row) * KPAD + u * 8));
    }
}

__global__ __launch_bounds__(256, 1) void argmin_mma_kernel(const float* __restrict__ x,
                                                            const float* __restrict__ emb,
                                                            const float* __restrict__ z,
                                                            float* __restrict__ out) {
    extern __shared__ __half sm[];
    // layout (halves): A[224*200] | B0[128*200] | B1[128*200] | ab(4096 f32) | Ci(224 f32)
    const int A_H = MROWS * SA;
    float* ab   = (float*)(sm + A_H + 2 * CHUNK * SA);
    float* Ci_s = ab + 2 * Kc;
    // post-loop aliases (regions no longer live):
    float* sred_s = (float*)(sm + A_H);            // [4][MROWS] in B0
    int*   sred_i = (int*)(sm + A_H) + 4 * MROWS;
    int*   ids_s  = (int*)Ci_s;

    int tid  = threadIdx.x;
    int warp = tid >> 5, lane = tid & 31;
    int wn = warp & 3, wg = warp >> 2;
    int G    = gridDim.x;
    int t0   = (int)(((long long)BT * blockIdx.x) / G);
    int t1   = (int)(((long long)BT * (blockIdx.x + 1)) / G);
    int ntok = t1 - t0;

    uint32_t smbase = smem_u32(sm);
    uint32_t b0a = smbase + A_H * 2;
    uint32_t b1a = b0a + CHUNK * SA * 2;

    // chunk-0 B prefetch first (overlaps A build)
    prefetch_b(b0a, 0, tid);
    cp_commit();

    // a/b tables -> smem
    {
        const float4* ga4 = (const float4*)g_a;
        const float4* gb4 = (const float4*)g_b;
        #pragma unroll
        for (int q = 0; q < 2; q++) ((float4*)ab)[tid + 256 * q]        = ga4[tid + 256 * q];
        #pragma unroll
        for (int q = 0; q < 2; q++) ((float4*)(ab + Kc))[tid + 256 * q] = gb4[tid + 256 * q];
    }

    // A build: row tid (token t0+tid if valid, else zeros)
    if (tid < MROWS) {
        __half2* arow = (__half2*)(sm + tid * SA);
        if (tid < ntok) {
            const float* xr = x + (size_t)(t0 + tid) * Dm;
            float Ci = 0.0f;
            #pragma unroll
            for (int d = 0; d < Hh; d += 2) {
                float2 v = *(const float2*)(xr + d);
                Ci += v.x * v.x + v.y * v.y;
                float s0 = 16.0f * v.x, s1 = 16.0f * v.y;
                __half h0 = __float2half_rn(s0), h1 = __float2half_rn(s1);
                __half m0 = __float2half_rn(s0 - __half2float(h0));
                __half m1 = __float2half_rn(s1 - __half2float(h1));
                __half2 hh = __halves2half2(h0, h1);
                __half2 mm = __halves2half2(m0, m1);
                arow[(0 * Hh + d) >> 1] = hh;
                arow[(1 * Hh + d) >> 1] = mm;
                arow[(2 * Hh + d) >> 1] = hh;
            }
            #pragma unroll
            for (int d = 0; d < Hh; d += 4) {
                float4 v = *(const float4*)(xr + Hh + d);
                Ci += expf(v.x) + expf(v.y) + expf(v.z) + expf(v.w);
            }
            Ci_s[tid] = Ci;
        } else {
            #pragma unroll
            for (int q = 0; q < KPAD / 2; q++)
                arow[q] = __halves2half2(__ushort_as_half(0), __ushort_as_half(0));
            Ci_s[tid] = 0.0f;
        }
    }
    __syncthreads();   // A_s, ab, Ci_s ready

    // per-lane ldsm offsets
    // A: rows sub*32 + {0,16} + (lane&15), koff (lane>>4)*16B
    uint32_t a_base = smbase + ((lane & 15) * SA + (lane >> 4) * 8) * 2;
    // B: rows wn*32 + {0,16} + (lane&7) + ((lane>>4)<<3), koff ((lane>>3)&1)*16B
    uint32_t b_off = ((wn * 32 + (lane & 7) + ((lane >> 4) << 3)) * SA
                    + ((lane >> 3) & 1) * 8) * 2;

    int g  = lane >> 2, tc = lane & 3;

    // running best per owned subtile (local index ls = sub>>1) x 4 row-slots
    float best[4][4];
    int   bidx[4][4];
    #pragma unroll
    for (int s = 0; s < 4; s++)
        #pragma unroll
        for (int q = 0; q < 4; q++) { best[s][q] = 3.4e38f; bidx[s][q] = 0; }

    for (int ch = 0; ch < NCHK; ch++) {
        uint32_t bb = (ch & 1) ? b1a : b0a;

        if (ch < NCHK - 1) {
            prefetch_b((ch & 1) ? b0a : b1a, (ch + 1) * CHUNK, tid);
            cp_commit();
            cp_wait1();           // chunk ch landed
        } else {
            cp_wait0();
        }
        __syncthreads();          // visible block-wide

        // preload all B fragments for this chunk into registers (24 ldsm)
        uint32_t bf[KIT][8];
        #pragma unroll
        for (int k = 0; k < KIT; k++) {
            ldsm4(&bf[k][0], bb + b_off + (uint32_t)k * 32);
            ldsm4(&bf[k][4], bb + b_off + 16 * SA * 2 + (uint32_t)k * 32);
        }

        #pragma unroll
        for (int ls = 0; ls < 4; ls++) {
            int sub = 2 * ls + wg;
            if (sub >= NSUB) break;   // wg=1 has 3 subtiles

            float acc[2][4][4];
            #pragma unroll
            for (int mt = 0; mt < 2; mt++)
                #pragma unroll
                for (int nt = 0; nt < 4; nt++)
                    #pragma unroll
                    for (int c = 0; c < 4; c++) acc[mt][nt][c] = 0.0f;

            uint32_t a0 = a_base + (uint32_t)(sub * 32) * (SA * 2);
            uint32_t a1 = a0 + 16 * SA * 2;

            #pragma unroll
            for (int k = 0; k < KIT; k++) {
                uint32_t kb = (uint32_t)k * 32;       // 16 halves
                uint32_t af0[4], af1[4];
                ldsm4(af0, a0 + kb);
                ldsm4(af1, a1 + kb);
                mma16816(acc[0][0], af0, &bf[k][0]);
                mma16816(acc[0][1], af0, &bf[k][2]);
                mma16816(acc[0][2], af0, &bf[k][4]);
                mma16816(acc[0][3], af0, &bf[k][6]);
                mma16816(acc[1][0], af1, &bf[k][0]);
                mma16816(acc[1][1], af1, &bf[k][2]);
                mma16816(acc[1][2], af1, &bf[k][4]);
                mma16816(acc[1][3], af1, &bf[k][6]);
            }

            // fold scores (codes ascending; strict < keeps first min)
            int cb = ch * CHUNK + wn * 32 + 2 * tc;
            float CiA[4];
            #pragma unroll
            for (int q = 0; q < 4; q++)
                CiA[q] = Ci_s[sub * 32 + (q >> 1) * 16 + (q & 1) * 8 + g];
            #pragma unroll
            for (int nt = 0; nt < 4; nt++) {
                int c0 = cb + nt * 8;
                float a0v = ab[c0],     b0v = ab[Kc + c0];
                float a1v = ab[c0 + 1], b1v = ab[Kc + c0 + 1];
                #pragma unroll
                for (int mt = 0; mt < 2; mt++)
                    #pragma unroll
                    for (int c = 0; c < 4; c++) {
                        int slot = mt * 2 + (c >> 1);
                        float aa  = (c & 1) ? a1v : a0v;
                        float bbv = (c & 1) ? b1v : b0v;
                        float s = fmaf(aa, fmaf(-0.0078125f, acc[mt][nt][c], CiA[slot]), bbv);
                        int code = c0 + (c & 1);
                        if (s < best[ls][slot]) { best[ls][slot] = s; bidx[ls][slot] = code; }
                    }
            }
        }
        __syncthreads();          // all reads of bb done before it is overwritten
    }

    // reduce across the 4 tc-lanes sharing each token row; stage per-wn
    #pragma unroll
    for (int ls = 0; ls < 4; ls++) {
        int sub = 2 * ls + wg;
        if (sub >= NSUB) break;
        #pragma unroll
        for (int s = 0; s < 4; s++) {
            float v = best[ls][s];
            int   c = bidx[ls][s];
            #pragma unroll
            for (int o = 1; o < 4; o <<= 1) {
                float v2 = __shfl_xor_sync(0xffffffffu, v, o);
                int   c2 = __shfl_xor_sync(0xffffffffu, c, o);
                if (v2 < v || (v2 == v && c2 < c)) { v = v2; c = c2; }
            }
            if (tc == 0) {
                int row = sub * 32 + (s >> 1) * 16 + (s & 1) * 8 + g;
                sred_s[wn * MROWS + row] = v;
                sred_i[wn * MROWS + row] = c;
            }
        }
    }
    __syncthreads();

    if (tid < MROWS) {
        float v = sred_s[tid];
        int   c = sred_i[tid];
        #pragma unroll
        for (int w = 1; w < 4; w++) {
            float v2 = sred_s[w * MROWS + tid];
            int   c2 = sred_i[w * MROWS + tid];
            if (v2 < v || (v2 == v && c2 < c)) { v = v2; c = c2; }
        }
        ids_s[tid] = c;
    }
    __syncthreads();

    // ---- fused epilogue: one warp per token ----
    for (int t = warp; t < ntok; t += 8) {
        int token = t0 + t;
        int id = ids_s[t];
        const float* w  = emb + (size_t)id * Dm;
        const float* xr = x + (size_t)token * Dm;

        float4 wv = *(const float4*)(w  + lane * 4);
        float4 xv = *(const float4*)(xr + lane * 4);
        float d0 = wv.x - xv.x, d1 = wv.y - xv.y, d2 = wv.z - xv.z, d3 = wv.w - xv.w;
        float p = d0 * d0 + d1 * d1 + d2 * d2 + d3 * d3;
        #pragma unroll
        for (int o = 16; o; o >>= 1) p += __shfl_xor_sync(0xffffffffu, p, o);

        #pragma unroll
        for (int r = 0; r < 2; r++) {
            int h = lane + 32 * r;
            float mu = w[h];
            float lv = w[Hh + h];
            float zz = z[(size_t)token * Hh + h];
            out[(size_t)token * Hh + h] = fmaf(expf(0.5f * lv), zz, mu);
        }
        if (lane == 0) {
            float m = p * (1.0f / (float)Dm);
            out[OUT_IDS  + token] = (float)id;
            out[OUT_COMM + token] = m;
            out[OUT_CODE + token] = m;
        }
    }
}

// --------------------------------------------------------------------------
extern "C" void kernel_launch(void* const* d_in, const int* in_sizes, int n_in,
                              void* d_out, int out_size) {
    const float *x = nullptr, *emb = nullptr, *z = nullptr;
    for (int i = 0; i < n_in; i++) {
        if (in_sizes[i] == BT * Dm)      x   = (const float*)d_in[i];
        else if (in_sizes[i] == Kc * Dm) emb = (const float*)d_in[i];
        else if (in_sizes[i] == BT * Hh) z   = (const float*)d_in[i];
    }
    float* out = (float*)d_out;

    int nsm = 148;
    cudaDeviceGetAttribute(&nsm, cudaDevAttrMultiProcessorCount, 0);
    if (nsm < 147) nsm = 147;   // MROWS=224 supports ntok <= 223

    // dyn smem: (224 + 2*128) rows * 200 halves + ab tables + Ci
    const int SMEM_BYTES = (MROWS + 2 * CHUNK) * SA * 2 + 2 * Kc * 4 + MROWS * 4;
    cudaFuncSetAttribute(argmin_mma_kernel,
                         cudaFuncAttributeMaxDynamicSharedMemorySize, SMEM_BYTES);

    prologue_kernel<<<Kc / 8, 256>>>(emb);
    argmin_mma_kernel<<<nsm, 256, SMEM_BYTES>>>(x, emb, z, out);
    (void)out_size;
}

// round 15
// speedup vs baseline: 1.2124x; 1.0698x over previous
#include <cuda_runtime.h>
#include <cuda_fp16.h>
#include <math.h>
#include <stdint.h>

// Problem constants (fixed shapes)
#define BT   32768      // B*T
#define Dm   128
#define Hh   64
#define Kc   2048

#define MROWS  224      // max A rows per CTA (7 subtiles of 32; max ntok 223 at grid>=147)
#define NSUB   7
#define CHUNK  128      // codes per B chunk
#define NCHK   (Kc / CHUNK)    // 16
#define KPAD   192      // concatenated K (3 segments of 64: hh, mh, hm)
#define KIT    (KPAD / 16)     // 12 k-iterations
#define SA     200      // smem row stride in halves (400B; 400%128=16 -> ldsm conflict-free)

// Output layout (float32 tuple: out, ids, commitment, codebook)
#define OUT_IDS   (BT * Hh)
#define OUT_COMM  (OUT_IDS + BT)
#define OUT_CODE  (OUT_COMM + BT)

// Device scratch
__device__ __align__(16) float g_a[Kc];
__device__ __align__(16) float g_b[Kc];
// B_cat: per code 192 fp16 = segments [wh, wh, wm] of (16*w_d)
__device__ __align__(16) __half g_bcat[Kc * KPAD];

// --------------------------------------------------------------------------
// PTX helpers — all plain sm_80-era features (legal on target compute_103)
// --------------------------------------------------------------------------
__device__ __forceinline__ uint32_t smem_u32(const void* p) {
    uint32_t a;
    asm("{ .reg .u64 t; cvta.to.shared.u64 t, %1; cvt.u32.u64 %0, t; }"
        : "=r"(a) : "l"(p));
    return a;
}
__device__ __forceinline__ void cp16s(uint32_t dst, const void* src) {
    asm volatile("cp.async.cg.shared.global [%0], [%1], 16;" :: "r"(dst), "l"(src));
}
__device__ __forceinline__ void cp_commit() { asm volatile("cp.async.commit_group;"); }
__device__ __forceinline__ void cp_wait1()  { asm volatile("cp.async.wait_group 1;" ::: "memory"); }
__device__ __forceinline__ void cp_wait0()  { asm volatile("cp.async.wait_group 0;" ::: "memory"); }

__device__ __forceinline__ void ldsm4(uint32_t* r, uint32_t addr) {
    asm volatile("ldmatrix.sync.aligned.m8n8.x4.shared.b16 {%0,%1,%2,%3}, [%4];"
        : "=r"(r[0]), "=r"(r[1]), "=r"(r[2]), "=r"(r[3]) : "r"(addr));
}
__device__ __forceinline__ void mma16816(float* d, const uint32_t* a, const uint32_t* b) {
    asm volatile(
        "mma.sync.aligned.m16n8k16.row.col.f32.f16.f16.f32 "
        "{%0,%1,%2,%3}, {%4,%5,%6,%7}, {%8,%9}, {%0,%1,%2,%3};"
        : "+f"(d[0]), "+f"(d[1]), "+f"(d[2]), "+f"(d[3])
        : "r"(a[0]), "r"(a[1]), "r"(a[2]), "r"(a[3]), "r"(b[0]), "r"(b[1]));
}

// --------------------------------------------------------------------------
// Kernel 1: merged prologue. One warp per code (8 codes / 256-thread block).
//   a_k = 1/(2*sum exp(w_lv)),  b_k = 0.5*sum(w_lv) + ||mu_e||^2 * a_k
//   B_cat limbs of 16*w: segments [wh, wh, wm]
// --------------------------------------------------------------------------
__global__ __launch_bounds__(256) void prologue_kernel(const float* __restrict__ emb) {
    int k    = blockIdx.x * 8 + (threadIdx.x >> 5);
    int lane = threadIdx.x & 31;
    if (k >= Kc) return;
    const float* row = emb + (size_t)k * Dm;
    float2 mu = *(const float2*)(row + 2 * lane);
    float2 lv = *(const float2*)(row + Hh + 2 * lane);

    {
        __half* o = g_bcat + (size_t)k * KPAD;
        float s0 = 16.0f * mu.x, s1 = 16.0f * mu.y;
        __half h0 = __float2half_rn(s0), h1 = __float2half_rn(s1);
        __half m0 = __float2half_rn(s0 - __half2float(h0));
        __half m1 = __float2half_rn(s1 - __half2float(h1));
        __half2* o2 = (__half2*)o;
        o2[(0 * Hh >> 1) + lane] = __halves2half2(h0, h1);
        o2[(1 * Hh >> 1) + lane] = __halves2half2(h0, h1);
        o2[(2 * Hh >> 1) + lane] = __halves2half2(m0, m1);
    }

    float e2 = mu.x * mu.x + mu.y * mu.y;
    float se = expf(lv.x) + expf(lv.y);
    float sl = lv.x + lv.y;
    #pragma unroll
    for (int o = 16; o; o >>= 1) {
        e2 += __shfl_xor_sync(0xffffffffu, e2, o);
        se += __shfl_xor_sync(0xffffffffu, se, o);
        sl += __shfl_xor_sync(0xffffffffu, sl, o);
    }
    if (lane == 0) {
        float a = 0.5f / se;
        g_a[k] = a;
        g_b[k] = 0.5f * sl + e2 * a;
    }
}

// --------------------------------------------------------------------------
// Kernel 2: persistent HMMA argmin + fused epilogue. grid = #SMs, 256 thr.
// CTA owns tokens [t0, t1) (<=223), padded to 7 m32-subtiles.
// Warp roles: wn = warp&3 owns codes [wn*32, wn*32+32) of the chunk;
// wg = warp>>2 owns subtiles sub ≡ wg (mod 2).
// Loop nest: k OUTER (B frags loaded once per k, 8 regs), subtiles inner,
// persistent acc[4][2][4][4] — deterministic ~196 regs, no spills.
// --------------------------------------------------------------------------
__device__ __forceinline__ void prefetch_b(uint32_t bbase, int c0, int tid) {
    #pragma unroll
    for (int q = 0; q < 12; q++) {
        int idx = tid + 256 * q;          // 0..3071 16B units
        int row = idx / 24, u = idx % 24;
        cp16s(bbase + row * (SA * 2) + u * 16,
              g_bcat + ((size_t)(c0 + row) * KPAD + u * 8));
    }
}

__global__ __launch_bounds__(256, 1) void argmin_mma_kernel(const float* __restrict__ x,
                                                            const float* __restrict__ emb,
                                                            const float* __restrict__ z,
                                                            float* __restrict__ out) {
    extern __shared__ __half sm[];
    // layout (halves): A[224*200] | B0[128*200] | B1[128*200] | ab(4096 f32) | Ci(224 f32)
    const int A_H = MROWS * SA;
    float* ab   = (float*)(sm + A_H + 2 * CHUNK * SA);
    float* Ci_s = ab + 2 * Kc;
    // post-loop aliases (regions no longer live):
    float* sred_s = (float*)(sm + A_H);            // [4][MROWS] in B0
    int*   sred_i = (int*)(sm + A_H) + 4 * MROWS;
    int*   ids_s  = (int*)Ci_s;

    int tid  = threadIdx.x;
    int warp = tid >> 5, lane = tid & 31;
    int wn = warp & 3, wg = warp >> 2;
    int G    = gridDim.x;
    int t0   = (int)(((long long)BT * blockIdx.x) / G);
    int t1   = (int)(((long long)BT * (blockIdx.x + 1)) / G);
    int ntok = t1 - t0;

    uint32_t smbase = smem_u32(sm);
    uint32_t b0a = smbase + A_H * 2;
    uint32_t b1a = b0a + CHUNK * SA * 2;

    // chunk-0 B prefetch first (overlaps A build)
    prefetch_b(b0a, 0, tid);
    cp_commit();

    // a/b tables -> smem
    {
        const float4* ga4 = (const float4*)g_a;
        const float4* gb4 = (const float4*)g_b;
        #pragma unroll
        for (int q = 0; q < 2; q++) ((float4*)ab)[tid + 256 * q]        = ga4[tid + 256 * q];
        #pragma unroll
        for (int q = 0; q < 2; q++) ((float4*)(ab + Kc))[tid + 256 * q] = gb4[tid + 256 * q];
    }

    // A build: row tid (token t0+tid if valid, else zeros)
    if (tid < MROWS) {
        __half2* arow = (__half2*)(sm + tid * SA);
        if (tid < ntok) {
            const float* xr = x + (size_t)(t0 + tid) * Dm;
            float Ci = 0.0f;
            #pragma unroll
            for (int d = 0; d < Hh; d += 2) {
                float2 v = *(const float2*)(xr + d);
                Ci += v.x * v.x + v.y * v.y;
                float s0 = 16.0f * v.x, s1 = 16.0f * v.y;
                __half h0 = __float2half_rn(s0), h1 = __float2half_rn(s1);
                __half m0 = __float2half_rn(s0 - __half2float(h0));
                __half m1 = __float2half_rn(s1 - __half2float(h1));
                __half2 hh = __halves2half2(h0, h1);
                __half2 mm = __halves2half2(m0, m1);
                arow[(0 * Hh + d) >> 1] = hh;
                arow[(1 * Hh + d) >> 1] = mm;
                arow[(2 * Hh + d) >> 1] = hh;
            }
            #pragma unroll
            for (int d = 0; d < Hh; d += 4) {
                float4 v = *(const float4*)(xr + Hh + d);
                Ci += expf(v.x) + expf(v.y) + expf(v.z) + expf(v.w);
            }
            Ci_s[tid] = Ci;
        } else {
            #pragma unroll
            for (int q = 0; q < KPAD / 2; q++)
                arow[q] = __halves2half2(__ushort_as_half(0), __ushort_as_half(0));
            Ci_s[tid] = 0.0f;
        }
    }
    __syncthreads();   // A_s, ab, Ci_s ready

    // per-lane ldsm offsets
    // A: rows sub*32 + {0,16} + (lane&15), koff (lane>>4)*16B
    uint32_t a_base = smbase + ((lane & 15) * SA + (lane >> 4) * 8) * 2;
    // B: rows wn*32 + {0,16} + (lane&7) + ((lane>>4)<<3), koff ((lane>>3)&1)*16B
    uint32_t b_off = ((wn * 32 + (lane & 7) + ((lane >> 4) << 3)) * SA
                    + ((lane >> 3) & 1) * 8) * 2;

    int g  = lane >> 2, tc = lane & 3;
    int nls = (wg == 0) ? 4 : 3;   // wg=0: subs 0,2,4,6; wg=1: subs 1,3,5

    // running best per owned subtile (local index ls) x 4 row-slots
    float best[4][4];
    int   bidx[4][4];
    #pragma unroll
    for (int s = 0; s < 4; s++)
        #pragma unroll
        for (int q = 0; q < 4; q++) { best[s][q] = 3.4e38f; bidx[s][q] = 0; }

    for (int ch = 0; ch < NCHK; ch++) {
        uint32_t bb = (ch & 1) ? b1a : b0a;

        if (ch < NCHK - 1) {
            prefetch_b((ch & 1) ? b0a : b1a, (ch + 1) * CHUNK, tid);
            cp_commit();
            cp_wait1();           // chunk ch landed
        } else {
            cp_wait0();
        }
        __syncthreads();          // visible block-wide

        // persistent accumulators for all owned subtiles
        float acc[4][2][4][4];
        #pragma unroll
        for (int ls = 0; ls < 4; ls++)
            #pragma unroll
            for (int mt = 0; mt < 2; mt++)
                #pragma unroll
                for (int nt = 0; nt < 4; nt++)
                    #pragma unroll
                    for (int c = 0; c < 4; c++) acc[ls][mt][nt][c] = 0.0f;

        // k OUTER: one B-frag load per k, swept over all owned subtiles
        #pragma unroll 1
        for (int k = 0; k < KIT; k++) {
            uint32_t kb = (uint32_t)k * 32;       // 16 halves
            uint32_t bf[8];
            ldsm4(&bf[0], bb + b_off + kb);
            ldsm4(&bf[4], bb + b_off + 16 * SA * 2 + kb);
            #pragma unroll
            for (int ls = 0; ls < 4; ls++) {
                if (ls >= nls) break;
                int sub = 2 * ls + wg;
                uint32_t a0 = a_base + (uint32_t)(sub * 32) * (SA * 2) + kb;
                uint32_t af0[4], af1[4];
                ldsm4(af0, a0);
                ldsm4(af1, a0 + 16 * SA * 2);
                mma16816(acc[ls][0][0], af0, &bf[0]);
                mma16816(acc[ls][0][1], af0, &bf[2]);
                mma16816(acc[ls][0][2], af0, &bf[4]);
                mma16816(acc[ls][0][3], af0, &bf[6]);
                mma16816(acc[ls][1][0], af1, &bf[0]);
                mma16816(acc[ls][1][1], af1, &bf[2]);
                mma16816(acc[ls][1][2], af1, &bf[4]);
                mma16816(acc[ls][1][3], af1, &bf[6]);
            }
        }

        // fold scores (codes ascending; strict < keeps first min)
        #pragma unroll
        for (int ls = 0; ls < 4; ls++) {
            if (ls >= nls) break;
            int sub = 2 * ls + wg;
            int cb = ch * CHUNK + wn * 32 + 2 * tc;
            float CiA[4];
            #pragma unroll
            for (int q = 0; q < 4; q++)
                CiA[q] = Ci_s[sub * 32 + (q >> 1) * 16 + (q & 1) * 8 + g];
            #pragma unroll
            for (int nt = 0; nt < 4; nt++) {
                int c0 = cb + nt * 8;
                float a0v = ab[c0],     b0v = ab[Kc + c0];
                float a1v = ab[c0 + 1], b1v = ab[Kc + c0 + 1];
                #pragma unroll
                for (int mt = 0; mt < 2; mt++)
                    #pragma unroll
                    for (int c = 0; c < 4; c++) {
                        int slot = mt * 2 + (c >> 1);
                        float aa  = (c & 1) ? a1v : a0v;
                        float bbv = (c & 1) ? b1v : b0v;
                        float s = fmaf(aa, fmaf(-0.0078125f, acc[ls][mt][nt][c], CiA[slot]), bbv);
                        int code = c0 + (c & 1);
                        if (s < best[ls][slot]) { best[ls][slot] = s; bidx[ls][slot] = code; }
                    }
            }
        }
        __syncthreads();          // all reads of bb done before it is overwritten
    }

    // reduce across the 4 tc-lanes sharing each token row; stage per-wn
    #pragma unroll
    for (int ls = 0; ls < 4; ls++) {
        if (ls >= nls) break;
        int sub = 2 * ls + wg;
        #pragma unroll
        for (int s = 0; s < 4; s++) {
            float v = best[ls][s];
            int   c = bidx[ls][s];
            #pragma unroll
            for (int o = 1; o < 4; o <<= 1) {
                float v2 = __shfl_xor_sync(0xffffffffu, v, o);
                int   c2 = __shfl_xor_sync(0xffffffffu, c, o);
                if (v2 < v || (v2 == v && c2 < c)) { v = v2; c = c2; }
            }
            if (tc == 0) {
                int row = sub * 32 + (s >> 1) * 16 + (s & 1) * 8 + g;
                sred_s[wn * MROWS + row] = v;
                sred_i[wn * MROWS + row] = c;
            }
        }
    }
    __syncthreads();

    if (tid < MROWS) {
        float v = sred_s[tid];
        int   c = sred_i[tid];
        #pragma unroll
        for (int w = 1; w < 4; w++) {
            float v2 = sred_s[w * MROWS + tid];
            int   c2 = sred_i[w * MROWS + tid];
            if (v2 < v || (v2 == v && c2 < c)) { v = v2; c = c2; }
        }
        ids_s[tid] = c;
    }
    __syncthreads();

    // ---- fused epilogue: one warp per token ----
    for (int t = warp; t < ntok; t += 8) {
        int token = t0 + t;
        int id = ids_s[t];
        const float* w  = emb + (size_t)id * Dm;
        const float* xr = x + (size_t)token * Dm;

        float4 wv = *(const float4*)(w  + lane * 4);
        float4 xv = *(const float4*)(xr + lane * 4);
        float d0 = wv.x - xv.x, d1 = wv.y - xv.y, d2 = wv.z - xv.z, d3 = wv.w - xv.w;
        float p = d0 * d0 + d1 * d1 + d2 * d2 + d3 * d3;
        #pragma unroll
        for (int o = 16; o; o >>= 1) p += __shfl_xor_sync(0xffffffffu, p, o);

        #pragma unroll
        for (int r = 0; r < 2; r++) {
            int h = lane + 32 * r;
            float mu = w[h];
            float lv = w[Hh + h];
            float zz = z[(size_t)token * Hh + h];
            out[(size_t)token * Hh + h] = fmaf(expf(0.5f * lv), zz, mu);
        }
        if (lane == 0) {
            float m = p * (1.0f / (float)Dm);
            out[OUT_IDS  + token] = (float)id;
            out[OUT_COMM + token] = m;
            out[OUT_CODE + token] = m;
        }
    }
}

// --------------------------------------------------------------------------
extern "C" void kernel_launch(void* const* d_in, const int* in_sizes, int n_in,
                              void* d_out, int out_size) {
    const float *x = nullptr, *emb = nullptr, *z = nullptr;
    for (int i = 0; i < n_in; i++) {
        if (in_sizes[i] == BT * Dm)      x   = (const float*)d_in[i];
        else if (in_sizes[i] == Kc * Dm) emb = (const float*)d_in[i];
        else if (in_sizes[i] == BT * Hh) z   = (const float*)d_in[i];
    }
    float* out = (float*)d_out;

    int nsm = 148;
    cudaDeviceGetAttribute(&nsm, cudaDevAttrMultiProcessorCount, 0);
    if (nsm < 147) nsm = 147;   // MROWS=224 supports ntok <= 223

    // dyn smem: (224 + 2*128) rows * 200 halves + ab tables + Ci
    const int SMEM_BYTES = (MROWS + 2 * CHUNK) * SA * 2 + 2 * Kc * 4 + MROWS * 4;
    cudaFuncSetAttribute(argmin_mma_kernel,
                         cudaFuncAttributeMaxDynamicSharedMemorySize, SMEM_BYTES);

    prologue_kernel<<<Kc / 8, 256>>>(emb);
    argmin_mma_kernel<<<nsm, 256, SMEM_BYTES>>>(x, emb, z, out);
    (void)out_size;
}

// round 16
// speedup vs baseline: 1.3242x; 1.0922x over previous
#include <cuda_runtime.h>
#include <cuda_fp16.h>
#include <math.h>
#include <stdint.h>

// Problem constants (fixed shapes)
#define BT   32768      // B*T
#define Dm   128
#define Hh   64
#define Kc   2048

#define MROWS  224      // max A rows per CTA (7 subtiles of 32; max ntok 223 at grid>=147)
#define NSUB   7
#define CHUNK  128      // codes per B chunk
#define NCHK   (Kc / CHUNK)    // 16
#define KPAD   192      // concatenated K (3 segments of 64: hh, mh, hm)
#define KIT    (KPAD / 16)     // 12 k-iterations
#define SA     200      // smem row stride in halves (400B; 400%128=16 -> ldsm conflict-free)
#define NT     512      // threads per argmin CTA (16 warps: 4 wn x 4 wg)

// Output layout (float32 tuple: out, ids, commitment, codebook)
#define OUT_IDS   (BT * Hh)
#define OUT_COMM  (OUT_IDS + BT)
#define OUT_CODE  (OUT_COMM + BT)

// Device scratch
__device__ __align__(16) float g_a[Kc];
__device__ __align__(16) float g_b[Kc];
// B_cat: per code 192 fp16 = segments [wh, wh, wm] of (16*w_d)
__device__ __align__(16) __half g_bcat[Kc * KPAD];

// --------------------------------------------------------------------------
// PTX helpers — all plain sm_80-era features (legal on target compute_103)
// --------------------------------------------------------------------------
__device__ __forceinline__ uint32_t smem_u32(const void* p) {
    uint32_t a;
    asm("{ .reg .u64 t; cvta.to.shared.u64 t, %1; cvt.u32.u64 %0, t; }"
        : "=r"(a) : "l"(p));
    return a;
}
__device__ __forceinline__ void cp16s(uint32_t dst, const void* src) {
    asm volatile("cp.async.cg.shared.global [%0], [%1], 16;" :: "r"(dst), "l"(src));
}
__device__ __forceinline__ void cp_commit() { asm volatile("cp.async.commit_group;"); }
__device__ __forceinline__ void cp_wait1()  { asm volatile("cp.async.wait_group 1;" ::: "memory"); }
__device__ __forceinline__ void cp_wait0()  { asm volatile("cp.async.wait_group 0;" ::: "memory"); }

__device__ __forceinline__ void ldsm4(uint32_t* r, uint32_t addr) {
    asm volatile("ldmatrix.sync.aligned.m8n8.x4.shared.b16 {%0,%1,%2,%3}, [%4];"
        : "=r"(r[0]), "=r"(r[1]), "=r"(r[2]), "=r"(r[3]) : "r"(addr));
}
__device__ __forceinline__ void mma16816(float* d, const uint32_t* a, const uint32_t* b) {
    asm volatile(
        "mma.sync.aligned.m16n8k16.row.col.f32.f16.f16.f32 "
        "{%0,%1,%2,%3}, {%4,%5,%6,%7}, {%8,%9}, {%0,%1,%2,%3};"
        : "+f"(d[0]), "+f"(d[1]), "+f"(d[2]), "+f"(d[3])
        : "r"(a[0]), "r"(a[1]), "r"(a[2]), "r"(a[3]), "r"(b[0]), "r"(b[1]));
}

// --------------------------------------------------------------------------
// Kernel 1: merged prologue. One warp per code (8 codes / 256-thread block).
//   a_k = 1/(2*sum exp(w_lv)),  b_k = 0.5*sum(w_lv) + ||mu_e||^2 * a_k
//   B_cat limbs of 16*w: segments [wh, wh, wm]
// --------------------------------------------------------------------------
__global__ __launch_bounds__(256) void prologue_kernel(const float* __restrict__ emb) {
    int k    = blockIdx.x * 8 + (threadIdx.x >> 5);
    int lane = threadIdx.x & 31;
    if (k >= Kc) return;
    const float* row = emb + (size_t)k * Dm;
    float2 mu = *(const float2*)(row + 2 * lane);
    float2 lv = *(const float2*)(row + Hh + 2 * lane);

    {
        __half* o = g_bcat + (size_t)k * KPAD;
        float s0 = 16.0f * mu.x, s1 = 16.0f * mu.y;
        __half h0 = __float2half_rn(s0), h1 = __float2half_rn(s1);
        __half m0 = __float2half_rn(s0 - __half2float(h0));
        __half m1 = __float2half_rn(s1 - __half2float(h1));
        __half2* o2 = (__half2*)o;
        o2[(0 * Hh >> 1) + lane] = __halves2half2(h0, h1);
        o2[(1 * Hh >> 1) + lane] = __halves2half2(h0, h1);
        o2[(2 * Hh >> 1) + lane] = __halves2half2(m0, m1);
    }

    float e2 = mu.x * mu.x + mu.y * mu.y;
    float se = expf(lv.x) + expf(lv.y);
    float sl = lv.x + lv.y;
    #pragma unroll
    for (int o = 16; o; o >>= 1) {
        e2 += __shfl_xor_sync(0xffffffffu, e2, o);
        se += __shfl_xor_sync(0xffffffffu, se, o);
        sl += __shfl_xor_sync(0xffffffffu, sl, o);
    }
    if (lane == 0) {
        float a = 0.5f / se;
        g_a[k] = a;
        g_b[k] = 0.5f * sl + e2 * a;
    }
}

// --------------------------------------------------------------------------
// Kernel 2: persistent HMMA argmin + fused epilogue. grid = #SMs, 512 thr.
// CTA owns tokens [t0, t1) (<=223), padded to 7 m32-subtiles.
// 16 warps: wn = warp&3 owns codes [wn*32, wn*32+32); wg = warp>>2 owns
// subtiles {wg, wg+4} (wg=3 owns only sub 3). Each SMSP holds one warp of
// each wg for its wn -> 7 subtiles of MMA work per SMSP, 4 warps hide ldsm.
// k OUTER, persistent acc[2][2][4][4] (64 regs) -> fits 128-reg budget.
// --------------------------------------------------------------------------
__device__ __forceinline__ void prefetch_b(uint32_t bbase, int c0, int tid) {
    #pragma unroll
    for (int q = 0; q < 6; q++) {
        int idx = tid + NT * q;           // 0..3071 16B units
        int row = idx / 24, u = idx % 24;
        cp16s(bbase + row * (SA * 2) + u * 16,
              g_bcat + ((size_t)(c0 + row) * KPAD + u * 8));
    }
}

__global__ __launch_bounds__(NT, 1) void argmin_mma_kernel(const float* __restrict__ x,
                                                           const float* __restrict__ emb,
                                                           const float* __restrict__ z,
                                                           float* __restrict__ out) {
    extern __shared__ __half sm[];
    // layout (halves): A[224*200] | B0[128*200] | B1[128*200] | ab(4096 f32) | Ci(224 f32)
    const int A_H = MROWS * SA;
    float* ab   = (float*)(sm + A_H + 2 * CHUNK * SA);
    float* Ci_s = ab + 2 * Kc;
    // post-loop aliases (regions no longer live):
    float* sred_s = (float*)(sm + A_H);            // [4][MROWS] in B0
    int*   sred_i = (int*)(sm + A_H) + 4 * MROWS;
    int*   ids_s  = (int*)Ci_s;

    int tid  = threadIdx.x;
    int warp = tid >> 5, lane = tid & 31;
    int wn = warp & 3, wg = warp >> 2;     // wg in 0..3
    int G    = gridDim.x;
    int t0   = (int)(((long long)BT * blockIdx.x) / G);
    int t1   = (int)(((long long)BT * (blockIdx.x + 1)) / G);
    int ntok = t1 - t0;

    uint32_t smbase = smem_u32(sm);
    uint32_t b0a = smbase + A_H * 2;
    uint32_t b1a = b0a + CHUNK * SA * 2;

    // chunk-0 B prefetch first (overlaps A build)
    prefetch_b(b0a, 0, tid);
    cp_commit();

    // a/b tables -> smem (2048 floats each = 512 float4 each)
    {
        const float4* ga4 = (const float4*)g_a;
        const float4* gb4 = (const float4*)g_b;
        ((float4*)ab)[tid]        = ga4[tid];
        ((float4*)(ab + Kc))[tid] = gb4[tid];
    }

    // A build: row tid (token t0+tid if valid, else zeros)
    if (tid < MROWS) {
        __half2* arow = (__half2*)(sm + tid * SA);
        if (tid < ntok) {
            const float* xr = x + (size_t)(t0 + tid) * Dm;
            float Ci = 0.0f;
            #pragma unroll
            for (int d = 0; d < Hh; d += 2) {
                float2 v = *(const float2*)(xr + d);
                Ci += v.x * v.x + v.y * v.y;
                float s0 = 16.0f * v.x, s1 = 16.0f * v.y;
                __half h0 = __float2half_rn(s0), h1 = __float2half_rn(s1);
                __half m0 = __float2half_rn(s0 - __half2float(h0));
                __half m1 = __float2half_rn(s1 - __half2float(h1));
                __half2 hh = __halves2half2(h0, h1);
                __half2 mm = __halves2half2(m0, m1);
                arow[(0 * Hh + d) >> 1] = hh;
                arow[(1 * Hh + d) >> 1] = mm;
                arow[(2 * Hh + d) >> 1] = hh;
            }
            #pragma unroll
            for (int d = 0; d < Hh; d += 4) {
                float4 v = *(const float4*)(xr + Hh + d);
                Ci += expf(v.x) + expf(v.y) + expf(v.z) + expf(v.w);
            }
            Ci_s[tid] = Ci;
        } else {
            #pragma unroll
            for (int q = 0; q < KPAD / 2; q++)
                arow[q] = __halves2half2(__ushort_as_half(0), __ushort_as_half(0));
            Ci_s[tid] = 0.0f;
        }
    }
    __syncthreads();   // A_s, ab, Ci_s ready

    // per-lane ldsm offsets
    // A: rows sub*32 + {0,16} + (lane&15), koff (lane>>4)*16B
    uint32_t a_base = smbase + ((lane & 15) * SA + (lane >> 4) * 8) * 2;
    // B: rows wn*32 + {0,16} + (lane&7) + ((lane>>4)<<3), koff ((lane>>3)&1)*16B
    uint32_t b_off = ((wn * 32 + (lane & 7) + ((lane >> 4) << 3)) * SA
                    + ((lane >> 3) & 1) * 8) * 2;

    int g  = lane >> 2, tc = lane & 3;
    int nls = (wg == 3) ? 1 : 2;   // wg owns subs {wg, wg+4}; sub 7 doesn't exist

    // running best per owned subtile (local index ls) x 4 row-slots
    float best[2][4];
    int   bidx[2][4];
    #pragma unroll
    for (int s = 0; s < 2; s++)
        #pragma unroll
        for (int q = 0; q < 4; q++) { best[s][q] = 3.4e38f; bidx[s][q] = 0; }

    for (int ch = 0; ch < NCHK; ch++) {
        uint32_t bb = (ch & 1) ? b1a : b0a;

        if (ch < NCHK - 1) {
            prefetch_b((ch & 1) ? b0a : b1a, (ch + 1) * CHUNK, tid);
            cp_commit();
            cp_wait1();           // chunk ch landed
        } else {
            cp_wait0();
        }
        __syncthreads();          // visible block-wide

        // persistent accumulators for owned subtiles (64 regs)
        float acc[2][2][4][4];
        #pragma unroll
        for (int ls = 0; ls < 2; ls++)
            #pragma unroll
            for (int mt = 0; mt < 2; mt++)
                #pragma unroll
                for (int nt = 0; nt < 4; nt++)
                    #pragma unroll
                    for (int c = 0; c < 4; c++) acc[ls][mt][nt][c] = 0.0f;

        // k OUTER: one B-frag load per k, swept over owned subtiles
        #pragma unroll 1
        for (int k = 0; k < KIT; k++) {
            uint32_t kb = (uint32_t)k * 32;       // 16 halves
            uint32_t bf[8];
            ldsm4(&bf[0], bb + b_off + kb);
            ldsm4(&bf[4], bb + b_off + 16 * SA * 2 + kb);
            #pragma unroll
            for (int ls = 0; ls < 2; ls++) {
                if (ls >= nls) break;
                int sub = wg + 4 * ls;
                uint32_t a0 = a_base + (uint32_t)(sub * 32) * (SA * 2) + kb;
                uint32_t af0[4], af1[4];
                ldsm4(af0, a0);
                ldsm4(af1, a0 + 16 * SA * 2);
                mma16816(acc[ls][0][0], af0, &bf[0]);
                mma16816(acc[ls][0][1], af0, &bf[2]);
                mma16816(acc[ls][0][2], af0, &bf[4]);
                mma16816(acc[ls][0][3], af0, &bf[6]);
                mma16816(acc[ls][1][0], af1, &bf[0]);
                mma16816(acc[ls][1][1], af1, &bf[2]);
                mma16816(acc[ls][1][2], af1, &bf[4]);
                mma16816(acc[ls][1][3], af1, &bf[6]);
            }
        }

        // fold scores (codes ascending; strict < keeps first min)
        #pragma unroll
        for (int ls = 0; ls < 2; ls++) {
            if (ls >= nls) break;
            int sub = wg + 4 * ls;
            int cb = ch * CHUNK + wn * 32 + 2 * tc;
            float CiA[4];
            #pragma unroll
            for (int q = 0; q < 4; q++)
                CiA[q] = Ci_s[sub * 32 + (q >> 1) * 16 + (q & 1) * 8 + g];
            #pragma unroll
            for (int nt = 0; nt < 4; nt++) {
                int c0 = cb + nt * 8;
                float a0v = ab[c0],     b0v = ab[Kc + c0];
                float a1v = ab[c0 + 1], b1v = ab[Kc + c0 + 1];
                #pragma unroll
                for (int mt = 0; mt < 2; mt++)
                    #pragma unroll
                    for (int c = 0; c < 4; c++) {
                        int slot = mt * 2 + (c >> 1);
                        float aa  = (c & 1) ? a1v : a0v;
                        float bbv = (c & 1) ? b1v : b0v;
                        float s = fmaf(aa, fmaf(-0.0078125f, acc[ls][mt][nt][c], CiA[slot]), bbv);
                        int code = c0 + (c & 1);
                        if (s < best[ls][slot]) { best[ls][slot] = s; bidx[ls][slot] = code; }
                    }
            }
        }
        __syncthreads();          // all reads of bb done before it is overwritten
    }

    // reduce across the 4 tc-lanes sharing each token row; stage per-wn
    #pragma unroll
    for (int ls = 0; ls < 2; ls++) {
        if (ls >= nls) break;
        int sub = wg + 4 * ls;
        #pragma unroll
        for (int s = 0; s < 4; s++) {
            float v = best[ls][s];
            int   c = bidx[ls][s];
            #pragma unroll
            for (int o = 1; o < 4; o <<= 1) {
                float v2 = __shfl_xor_sync(0xffffffffu, v, o);
                int   c2 = __shfl_xor_sync(0xffffffffu, c, o);
                if (v2 < v || (v2 == v && c2 < c)) { v = v2; c = c2; }
            }
            if (tc == 0) {
                int row = sub * 32 + (s >> 1) * 16 + (s & 1) * 8 + g;
                sred_s[wn * MROWS + row] = v;
                sred_i[wn * MROWS + row] = c;
            }
        }
    }
    __syncthreads();

    if (tid < MROWS) {
        float v = sred_s[tid];
        int   c = sred_i[tid];
        #pragma unroll
        for (int w = 1; w < 4; w++) {
            float v2 = sred_s[w * MROWS + tid];
            int   c2 = sred_i[w * MROWS + tid];
            if (v2 < v || (v2 == v && c2 < c)) { v = v2; c = c2; }
        }
        ids_s[tid] = c;
    }
    __syncthreads();

    // ---- fused epilogue: one warp per token ----
    for (int t = warp; t < ntok; t += 16) {
        int token = t0 + t;
        int id = ids_s[t];
        const float* w  = emb + (size_t)id * Dm;
        const float* xr = x + (size_t)token * Dm;

        float4 wv = *(const float4*)(w  + lane * 4);
        float4 xv = *(const float4*)(xr + lane * 4);
        float d0 = wv.x - xv.x, d1 = wv.y - xv.y, d2 = wv.z - xv.z, d3 = wv.w - xv.w;
        float p = d0 * d0 + d1 * d1 + d2 * d2 + d3 * d3;
        #pragma unroll
        for (int o = 16; o; o >>= 1) p += __shfl_xor_sync(0xffffffffu, p, o);

        #pragma unroll
        for (int r = 0; r < 2; r++) {
            int h = lane + 32 * r;
            float mu = w[h];
            float lv = w[Hh + h];
            float zz = z[(size_t)token * Hh + h];
            out[(size_t)token * Hh + h] = fmaf(expf(0.5f * lv), zz, mu);
        }
        if (lane == 0) {
            float m = p * (1.0f / (float)Dm);
            out[OUT_IDS  + token] = (float)id;
            out[OUT_COMM + token] = m;
            out[OUT_CODE + token] = m;
        }
    }
}

// --------------------------------------------------------------------------
extern "C" void kernel_launch(void* const* d_in, const int* in_sizes, int n_in,
                              void* d_out, int out_size) {
    const float *x = nullptr, *emb = nullptr, *z = nullptr;
    for (int i = 0; i < n_in; i++) {
        if (in_sizes[i] == BT * Dm)      x   = (const float*)d_in[i];
        else if (in_sizes[i] == Kc * Dm) emb = (const float*)d_in[i];
        else if (in_sizes[i] == BT * Hh) z   = (const float*)d_in[i];
    }
    float* out = (float*)d_out;

    int nsm = 148;
    cudaDeviceGetAttribute(&nsm, cudaDevAttrMultiProcessorCount, 0);
    if (nsm < 147) nsm = 147;   // MROWS=224 supports ntok <= 223

    // dyn smem: (224 + 2*128) rows * 200 halves + ab tables + Ci
    const int SMEM_BYTES = (MROWS + 2 * CHUNK) * SA * 2 + 2 * Kc * 4 + MROWS * 4;
    cudaFuncSetAttribute(argmin_mma_kernel,
                         cudaFuncAttributeMaxDynamicSharedMemorySize, SMEM_BYTES);

    prologue_kernel<<<Kc / 8, 256>>>(emb);
    argmin_mma_kernel<<<nsm, NT, SMEM_BYTES>>>(x, emb, z, out);
    (void)out_size;
}